// round 15
// baseline (speedup 1.0000x reference)
#include <cuda_runtime.h>
#include <cuda_bf16.h>
#include <cstdint>

// ---------------------------------------------------------------------------
// ISTFTHead: h = x@W + b (bf16 mma.sync split-fp32 GEMM, K'=3*512);
// irfft(1024) via half-size 512-pt complex radix-8 iFFT; hann window;
// overlap-add hop 256; crop PAD=384; COLA envelope division.
// GEMM: CTA 256x128, 8 warps of 64x64, cp.async double-buffered tiles.
// ---------------------------------------------------------------------------

#define M_TOT   16384
#define K_DIM   512
#define KP      1536
#define N_DIM   1026
#define N_PAD   1152       // 9 * 128
#define NBINS   513
#define NFFT    1024
#define HOP     256
#define PADC    384
#define OUTL    524288
#define NB      8

__device__ float         g_h[M_TOT * (long)N_DIM];
__device__ float         g_frames[M_TOT * (long)NFFT];
__device__ __nv_bfloat16 g_Ah[M_TOT * (long)KP];
__device__ __nv_bfloat16 g_Bt[N_PAD * (long)KP];
__device__ float         g_twc[512], g_tws[512];     // e^{+2pi i k/1024}
__device__ float         g_t5c[512], g_t5s[512];     // e^{+2pi i m/512}
__device__ float         g_win[NFFT];

static __device__ __forceinline__ uint32_t s2u(const void* p)
{
    return (uint32_t)__cvta_generic_to_shared(p);
}

#define CP_ASYNC16(sm, gp) \
    asm volatile("cp.async.cg.shared.global [%0], [%1], 16;" :: "r"(sm), "l"(gp) : "memory")
#define CP_COMMIT() asm volatile("cp.async.commit_group;" ::: "memory")
#define CP_WAIT0()  asm volatile("cp.async.wait_group 0;" ::: "memory")

// ---------------------------------------------------------------------------
// Prepass A: split x into (hi, hi, lo) bf16 segments along K'.
// ---------------------------------------------------------------------------
__global__ __launch_bounds__(256) void conv_a_kernel(const float* __restrict__ x)
{
    const long idx = (long)blockIdx.x * 256 + threadIdx.x;
    if (idx >= (long)M_TOT * K_DIM) return;
    const long m = idx >> 9;
    const int  k = (int)(idx & 511);
    const float v = x[idx];
    __nv_bfloat16 hi = __float2bfloat16(v);
    __nv_bfloat16 lo = __float2bfloat16(v - __bfloat162float(hi));
    __nv_bfloat16* row = g_Ah + m * KP;
    row[k]        = hi;
    row[k + 512]  = hi;
    row[k + 1024] = lo;
}

// ---------------------------------------------------------------------------
// Prepass B: transposed padded B' (n-major): segments [hi_W | lo_W | hi_W].
// ---------------------------------------------------------------------------
__global__ __launch_bounds__(256) void conv_b_kernel(const float* __restrict__ W)
{
    const long idx = (long)blockIdx.x * 256 + threadIdx.x;
    if (idx >= (long)N_PAD * KP) return;
    const int n  = (int)(idx / KP);
    const int kp = (int)(idx - (long)n * KP);
    __nv_bfloat16 r = __float2bfloat16(0.0f);
    if (n < N_DIM) {
        const int seg = kp >> 9;
        const int k   = kp & 511;
        const float v = W[(long)k * N_DIM + n];
        __nv_bfloat16 hi = __float2bfloat16(v);
        if (seg == 1) r = __float2bfloat16(v - __bfloat162float(hi));
        else          r = hi;
    }
    g_Bt[idx] = r;
}

// ---------------------------------------------------------------------------
// Prepass C: twiddle + window tables (precise sincosf).
// ---------------------------------------------------------------------------
__global__ void init_tables_kernel()
{
    const int t = threadIdx.x;               // 0..1023
    const float ang = 6.2831853071795864769f * (float)t * (1.0f / 1024.0f);
    if (t < 512) {
        float s, c;
        sincosf(ang, &s, &c);
        g_twc[t] = c;
        g_tws[t] = s;
        float s2, c2;
        sincosf(6.2831853071795864769f * (float)t * (1.0f / 512.0f), &s2, &c2);
        g_t5c[t] = c2;
        g_t5s[t] = s2;
    }
    g_win[t] = 0.5f - 0.5f * cosf(ang);
}

// ---------------------------------------------------------------------------
// Kernel 1: bf16 mma GEMM.  CTA 256x128, 8 warps (4m x 2n) of 64x64 tiles.
// BK=32, cp.async double-buffered dynamic smem, ldmatrix.x4, pitch 40 halfs
// (80 B rows: conflict-free, measured in R7).
// Dyn smem layout (bytes): As[2] @0 (stride 20480), Bs[2] @40960 (stride 10240).
// ---------------------------------------------------------------------------
#define GEMM_DSMEM 61440

__global__ __launch_bounds__(256, 1) void gemm_mma_kernel(const float* __restrict__ bias)
{
    extern __shared__ __nv_bfloat16 dsm[];

    const int tid  = threadIdx.x;
    const int wid  = tid >> 5;
    const int lane = tid & 31;
    const int gid  = lane >> 2;
    const int tg   = lane & 3;

    const int warp_m = (wid >> 1) * 64;   // 0,64,128,192
    const int warp_n = (wid & 1) * 64;    // 0,64

    const long mbase = (long)blockIdx.y * 256;
    const int  nbase = blockIdx.x * 128;

    // cp.async fill mapping: A row per thread (4 chunks), B row per half (2 chunks)
    const int arow = tid;                 // 0..255
    const int brow = tid & 127;
    const int bsel = (tid >> 7) * 2;      // chunks {0,1} or {2,3}

    const __nv_bfloat16* gA = g_Ah + (mbase + arow) * (long)KP;
    const __nv_bfloat16* gB = g_Bt + (long)(nbase + brow) * KP + bsel * 8;

    const uint32_t smem0 = s2u(dsm);
    const uint32_t sAfill = smem0 + arow * 80;              // + buf*20480 + c*16
    const uint32_t sBfill = smem0 + 40960 + brow * 80 + bsel * 16;

    // ldmatrix lane addressing (same frag layout as R7)
    const int aR = (lane & 15);
    const int aC = (lane >> 4) << 3;
    const int bR = (lane & 7) + ((lane >> 4) << 3);
    const int bC = ((lane >> 3) & 1) << 3;
    const uint32_t aBase = smem0 + (warp_m + aR) * 80 + aC * 2;          // + buf*20480 + mi*1280 + k16*2
    const uint32_t bBase = smem0 + 40960 + (warp_n + bR) * 80 + bC * 2;  // + buf*10240 + np*1280 + k16*2

    float acc[4][4][2][4];
#pragma unroll
    for (int mi = 0; mi < 4; mi++)
#pragma unroll
        for (int np = 0; np < 4; np++)
#pragma unroll
            for (int s = 0; s < 2; s++)
#pragma unroll
                for (int e = 0; e < 4; e++) acc[mi][np][s][e] = 0.0f;

    // prologue: fill tile 0 into buf 0
    {
        const __nv_bfloat16* ga = gA;
#pragma unroll
        for (int c = 0; c < 4; c++)
            CP_ASYNC16(sAfill + c * 16, ga + c * 8);
        CP_ASYNC16(sBfill,      gB);
        CP_ASYNC16(sBfill + 16, gB + 8);
        CP_COMMIT();
        CP_WAIT0();
    }
    __syncthreads();

    for (int kt = 0; kt < 48; kt++) {
        const int cur = kt & 1, nxt = cur ^ 1;
        if (kt < 47) {
            const __nv_bfloat16* ga = gA + (kt + 1) * 32;
            const __nv_bfloat16* gb = gB + (kt + 1) * 32;
            const uint32_t sa = sAfill + nxt * 20480u;
            const uint32_t sb = sBfill + nxt * 10240u;
#pragma unroll
            for (int c = 0; c < 4; c++)
                CP_ASYNC16(sa + c * 16, ga + c * 8);
            CP_ASYNC16(sb,      gb);
            CP_ASYNC16(sb + 16, gb + 8);
            CP_COMMIT();
        }

        const uint32_t aB = aBase + cur * 20480u;
        const uint32_t bB = bBase + cur * 10240u;
#pragma unroll
        for (int k16 = 0; k16 < 32; k16 += 16) {
            uint32_t af[4][4];
#pragma unroll
            for (int mi = 0; mi < 4; mi++) {
                asm volatile(
                    "ldmatrix.sync.aligned.m8n8.x4.shared.b16 {%0,%1,%2,%3}, [%4];"
                    : "=r"(af[mi][0]), "=r"(af[mi][1]), "=r"(af[mi][2]), "=r"(af[mi][3])
                    : "r"(aB + mi * 1280 + k16 * 2));
            }
            uint32_t bf[4][4];
#pragma unroll
            for (int np = 0; np < 4; np++) {
                asm volatile(
                    "ldmatrix.sync.aligned.m8n8.x4.shared.b16 {%0,%1,%2,%3}, [%4];"
                    : "=r"(bf[np][0]), "=r"(bf[np][1]), "=r"(bf[np][2]), "=r"(bf[np][3])
                    : "r"(bB + np * 1280 + k16 * 2));
            }
#pragma unroll
            for (int mi = 0; mi < 4; mi++)
#pragma unroll
                for (int np = 0; np < 4; np++) {
                    asm volatile(
                        "mma.sync.aligned.m16n8k16.row.col.f32.bf16.bf16.f32 "
                        "{%0,%1,%2,%3}, {%4,%5,%6,%7}, {%8,%9}, {%0,%1,%2,%3};\n"
                        : "+f"(acc[mi][np][0][0]), "+f"(acc[mi][np][0][1]),
                          "+f"(acc[mi][np][0][2]), "+f"(acc[mi][np][0][3])
                        : "r"(af[mi][0]), "r"(af[mi][1]), "r"(af[mi][2]), "r"(af[mi][3]),
                          "r"(bf[np][0]), "r"(bf[np][1]));
                    asm volatile(
                        "mma.sync.aligned.m16n8k16.row.col.f32.bf16.bf16.f32 "
                        "{%0,%1,%2,%3}, {%4,%5,%6,%7}, {%8,%9}, {%0,%1,%2,%3};\n"
                        : "+f"(acc[mi][np][1][0]), "+f"(acc[mi][np][1][1]),
                          "+f"(acc[mi][np][1][2]), "+f"(acc[mi][np][1][3])
                        : "r"(af[mi][0]), "r"(af[mi][1]), "r"(af[mi][2]), "r"(af[mi][3]),
                          "r"(bf[np][2]), "r"(bf[np][3]));
                }
        }

        if (kt < 47) {
            CP_WAIT0();
            __syncthreads();
        }
    }

    // epilogue: bias + store (guard col < 1026)
#pragma unroll
    for (int mi = 0; mi < 4; mi++) {
        const long r0 = mbase + warp_m + mi * 16 + gid;
        const long r1 = r0 + 8;
#pragma unroll
        for (int np = 0; np < 4; np++)
#pragma unroll
            for (int s = 0; s < 2; s++) {
                const int c0 = nbase + warp_n + np * 16 + s * 8 + tg * 2;
                if (c0 < N_DIM) {
                    const float bb = bias[c0];
                    g_h[r0 * N_DIM + c0] = acc[mi][np][s][0] + bb;
                    g_h[r1 * N_DIM + c0] = acc[mi][np][s][2] + bb;
                }
                if (c0 + 1 < N_DIM) {
                    const float bb = bias[c0 + 1];
                    g_h[r0 * N_DIM + c0 + 1] = acc[mi][np][s][1] + bb;
                    g_h[r1 * N_DIM + c0 + 1] = acc[mi][np][s][3] + bb;
                }
            }
    }
}

// ---------------------------------------------------------------------------
// Kernel 2: half-size real iFFT.  4 frames per CTA (256 thr, 64 per frame).
//   Z[k] = (S[k]+conj(S[512-k])) + i e^{2pi ik/1024}(S[k]-conj(S[512-k]))
//   z = FFT512^{+}(Z), y[2n]=Re z[n]/1024, y[2n+1]=Im z[n]/1024.
//   FFT512 = 3 radix-8 DIT stages on base-8 digit-reversed input.
// ---------------------------------------------------------------------------
#define C45 0.70710678118654752440f

__global__ __launch_bounds__(256) void istft_frame_kernel()
{
    __shared__ float sSr[4][516], sSi[4][516];
    __shared__ float zr[4][512],  zi[4][512];
    __shared__ float t5c[512], t5s[512];

    const int tid = threadIdx.x;
    const int fl  = tid >> 6;        // frame lane 0..3
    const int t   = tid & 63;        // thread within frame
    const int f   = blockIdx.x * 4 + fl;

    t5c[tid]       = g_t5c[tid];
    t5s[tid]       = g_t5s[tid];
    t5c[tid + 256] = g_t5c[tid + 256];
    t5s[tid + 256] = g_t5s[tid + 256];

    const float* hrow = g_h + (long)f * N_DIM;

    // ---- S build (bins 0..512; bins 0,512 imag zeroed) ----
#pragma unroll
    for (int i = 0; i < 8; i++) {
        const int k = t + 64 * i;
        float mag = fminf(__expf(hrow[k]), 100.0f);
        float p = hrow[NBINS + k];
        float s, c;
        __sincosf(p, &s, &c);
        sSr[fl][k] = mag * c;
        sSi[fl][k] = (k == 0) ? 0.0f : mag * s;
    }
    if (t == 0) {
        float mag = fminf(__expf(hrow[512]), 100.0f);
        float p = hrow[NBINS + 512];
        float s, c;
        __sincosf(p, &s, &c);
        sSr[fl][512] = mag * c;
        sSi[fl][512] = 0.0f;
    }
    __syncthreads();

    // ---- Z build, scatter to base-8 digit-reversed positions ----
#pragma unroll
    for (int i = 0; i < 8; i++) {
        const int k = t + 64 * i;
        const float ar = sSr[fl][k],       ai = sSi[fl][k];
        const float br = sSr[fl][512 - k], bi = -sSi[fl][512 - k];
        const float sr = ar + br, si = ai + bi;
        const float dr = ar - br, di = ai - bi;
        const float wc = g_twc[k], ws = g_tws[k];       // e^{+2pi ik/1024}
        const float tr = dr * wc - di * ws;
        const float ti = dr * ws + di * wc;
        const int d = ((k & 7) << 6) | (k & 56) | (k >> 6);
        zr[fl][d] = sr - ti;
        zi[fl][d] = si + tr;
    }
    __syncthreads();

    // ---- 3 radix-8 DIT stages (inverse sign e^{+}) ----
#pragma unroll
    for (int st = 0; st < 3; st++) {
        const int q    = (st == 0) ? 1 : (st == 1) ? 8 : 64;
        const int msc  = (st == 0) ? 64 : (st == 1) ? 8 : 1;  // 512/(8q)
        const int pos  = t & (q - 1);
        const int base = (t / q) * (8 * q) + pos;

        float xr[8], xi[8];
#pragma unroll
        for (int j = 0; j < 8; j++) {
            float vr = zr[fl][base + j * q];
            float vi = zi[fl][base + j * q];
            if (j > 0) {
                const int m = pos * j * msc;
                const float c = t5c[m], s = t5s[m];
                const float nr = vr * c - vi * s;
                vi = vr * s + vi * c;
                vr = nr;
            }
            xr[j] = vr;
            xi[j] = vi;
        }

        float E0r, E0i, E1r, E1i, E2r, E2i, E3r, E3i;
        float O0r, O0i, O1r, O1i, O2r, O2i, O3r, O3i;
        {
            const float arr = xr[0] + xr[4], ari = xi[0] + xi[4];
            const float brr = xr[0] - xr[4], bri = xi[0] - xi[4];
            const float crr = xr[2] + xr[6], cri = xi[2] + xi[6];
            const float drr = xr[2] - xr[6], dri = xi[2] - xi[6];
            E0r = arr + crr;  E0i = ari + cri;
            E2r = arr - crr;  E2i = ari - cri;
            E1r = brr - dri;  E1i = bri + drr;
            E3r = brr + dri;  E3i = bri - drr;
        }
        {
            const float arr = xr[1] + xr[5], ari = xi[1] + xi[5];
            const float brr = xr[1] - xr[5], bri = xi[1] - xi[5];
            const float crr = xr[3] + xr[7], cri = xi[3] + xi[7];
            const float drr = xr[3] - xr[7], dri = xi[3] - xi[7];
            O0r = arr + crr;  O0i = ari + cri;
            O2r = arr - crr;  O2i = ari - cri;
            O1r = brr - dri;  O1i = bri + drr;
            O3r = brr + dri;  O3i = bri - drr;
        }
        const float w1r = C45 * (O1r - O1i), w1i = C45 * (O1r + O1i);
        const float w2r = -O2i,              w2i = O2r;
        const float w3r = -C45 * (O3r + O3i), w3i = C45 * (O3r - O3i);

        zr[fl][base]         = E0r + O0r;  zi[fl][base]         = E0i + O0i;
        zr[fl][base + 4 * q] = E0r - O0r;  zi[fl][base + 4 * q] = E0i - O0i;
        zr[fl][base + 1 * q] = E1r + w1r;  zi[fl][base + 1 * q] = E1i + w1i;
        zr[fl][base + 5 * q] = E1r - w1r;  zi[fl][base + 5 * q] = E1i - w1i;
        zr[fl][base + 2 * q] = E2r + w2r;  zi[fl][base + 2 * q] = E2i + w2i;
        zr[fl][base + 6 * q] = E2r - w2r;  zi[fl][base + 6 * q] = E2i - w2i;
        zr[fl][base + 3 * q] = E3r + w3r;  zi[fl][base + 3 * q] = E3i + w3i;
        zr[fl][base + 7 * q] = E3r - w3r;  zi[fl][base + 7 * q] = E3i - w3i;
        __syncthreads();
    }

    // ---- windowed output ----
    float* frow = g_frames + (long)f * NFFT;
#pragma unroll
    for (int i = 0; i < 8; i++) {
        const int n = t + 64 * i;
        float2 v;
        v.x = zr[fl][n] * (1.0f / 1024.0f) * g_win[2 * n];
        v.y = zi[fl][n] * (1.0f / 1024.0f) * g_win[2 * n + 1];
        *(float2*)(frow + 2 * n) = v;
    }
}

// ---------------------------------------------------------------------------
// Kernel 3: overlap-add + envelope (interior env == 1.5 exactly).
// ---------------------------------------------------------------------------
__global__ __launch_bounds__(256) void ola_kernel(float* __restrict__ out)
{
    const int idx = blockIdx.x * blockDim.x + threadIdx.x;
    if (idx >= NB * OUTL) return;
    const int b = idx / OUTL;
    const int i = idx - b * OUTL;
    const int n = i + PADC;

    const int tmax = min(n >> 8, 2047);
    const int tmin = (n >= NFFT) ? ((n - (NFFT - 1) + (HOP - 1)) >> 8) : 0;

    float sum = 0.0f;
#pragma unroll 4
    for (int t = tmin; t <= tmax; ++t) {
        const int m = n - (t << 8);
        sum += g_frames[(((long)(b * 2048 + t)) << 10) + m];
    }

    float env;
    if (tmax - tmin == 3) {
        env = 1.5f;
    } else {
        env = 0.0f;
        for (int t = tmin; t <= tmax; ++t) {
            const int m = n - (t << 8);
            float w = 0.5f - 0.5f * cosf(6.2831853071795864769f * (float)m * (1.0f / 1024.0f));
            env += w * w;
        }
    }
    out[idx] = sum / env;
}

// ---------------------------------------------------------------------------
extern "C" void kernel_launch(void* const* d_in, const int* in_sizes, int n_in,
                              void* d_out, int out_size)
{
    const float* x    = (const float*)d_in[0];
    const float* W    = (const float*)d_in[1];
    const float* bias = (const float*)d_in[2];
    float* out = (float*)d_out;

    // idempotent attribute set (not an allocation; not a captured stream op)
    cudaFuncSetAttribute(gemm_mma_kernel,
                         cudaFuncAttributeMaxDynamicSharedMemorySize, GEMM_DSMEM);

    const long na = (long)M_TOT * K_DIM;
    conv_a_kernel<<<(unsigned)((na + 255) / 256), 256>>>(x);
    const long nb = (long)N_PAD * KP;
    conv_b_kernel<<<(unsigned)((nb + 255) / 256), 256>>>(W);
    init_tables_kernel<<<1, 1024>>>();

    dim3 gg(N_PAD / 128, M_TOT / 256);           // (9, 64)
    gemm_mma_kernel<<<gg, 256, GEMM_DSMEM>>>(bias);

    istft_frame_kernel<<<M_TOT / 4, 256>>>();

    const int total = NB * OUTL;
    ola_kernel<<<(total + 255) / 256, 256>>>(out);
}